// round 7
// baseline (speedup 1.0000x reference)
#include <cuda_runtime.h>
#include <cstdint>

#define NUM_OUTPUTS 1032
#define D4 258              // 1032 floats = 258 float4 per weight row
#define CHUNK 86            // float4 per column chunk (3 chunks: 86*3 = 258)
#define CHUNK_BYTES (CHUNK * 16)   // 1376
#define NCHUNK 3
#define MAX_ACTIVE 32
#define K_LDG 24            // features gathered via LDG (L1tex path)
#define K_BULK 8            // features gathered via cp.async.bulk (LTS path)
#define BATCH 4096
#define THREADS 96          // 3 warps; lanes 0..85 active

__device__ __forceinline__ uint32_t smem_u32(const void* p) {
    return (uint32_t)__cvta_generic_to_shared(p);
}

__global__ __launch_bounds__(THREADS)
void ft_hybrid_kernel(const int*    __restrict__ idx0,
                      const float*  __restrict__ val0,
                      const int*    __restrict__ idx1,
                      const float*  __restrict__ val1,
                      const float4* __restrict__ W4,
                      const float4* __restrict__ bias4,
                      float4*       __restrict__ out4)
{
    const int r     = blockIdx.x;          // 0..8191 : both feature sets fused
    const int chunk = blockIdx.y;          // 0..2    : slow dim -> L2 phases
    const int tid   = threadIdx.x;

    const int*   idx;
    const float* val;
    int row;
    if (r < BATCH) { idx = idx0; val = val0; row = r; }
    else           { idx = idx1; val = val1; row = r - BATCH; }

    __shared__ int   sOff[MAX_ACTIVE];     // row offsets in float4 units
    __shared__ float sVal[MAX_ACTIVE];
    __shared__ alignas(16) float sW[K_BULK][CHUNK * 4];   // 8 x 1376 B
    __shared__ alignas(8) unsigned long long mbar;

    if (tid == 0) {
        uint32_t mb = smem_u32(&mbar);
        asm volatile("mbarrier.init.shared.b64 [%0], %1;" :: "r"(mb), "r"(1) : "memory");
    }
    if (tid < MAX_ACTIVE) {
        sOff[tid] = idx[row * MAX_ACTIVE + tid] * D4;
        sVal[tid] = val[row * MAX_ACTIVE + tid];
    }
    __syncthreads();

    const int c = chunk * CHUNK + tid;     // float4 column index (valid if tid<CHUNK)

    // Thread 0: kick off the bulk (LTS-path) gathers for features K_LDG..31.
    if (tid == 0) {
        uint32_t mb = smem_u32(&mbar);
        asm volatile("mbarrier.arrive.expect_tx.shared.b64 _, [%0], %1;"
                     :: "r"(mb), "r"((uint32_t)(K_BULK * CHUNK_BYTES)) : "memory");
        #pragma unroll
        for (int j = 0; j < K_BULK; ++j) {
            const char* src = (const char*)W4 + ((size_t)(uint32_t)sOff[K_LDG + j] + chunk * CHUNK) * 16;
            uint32_t dst = smem_u32(&sW[j][0]);
            asm volatile(
                "cp.async.bulk.shared::cluster.global.mbarrier::complete_tx::bytes "
                "[%0], [%1], %2, [%3];"
                :: "r"(dst), "l"(src), "r"((uint32_t)CHUNK_BYTES), "r"(smem_u32(&mbar))
                : "memory");
        }
    }

    if (tid >= CHUNK) return;              // inactive lanes exit (no barriers below)

    float4 a = bias4[c];
    const float4* __restrict__ Wc = W4 + c;

    // LDG/L1 path: 24 features, overlapped with the bulk copies above.
    #pragma unroll 8
    for (int k = 0; k < K_LDG; ++k) {
        const float4 w = __ldg(Wc + sOff[k]);
        const float  v = sVal[k];
        a.x = fmaf(w.x, v, a.x);
        a.y = fmaf(w.y, v, a.y);
        a.z = fmaf(w.z, v, a.z);
        a.w = fmaf(w.w, v, a.w);
    }

    // Wait for bulk copies (parity 0, single use per block).
    {
        uint32_t mb = smem_u32(&mbar);
        uint32_t done;
        asm volatile(
            "{\n\t"
            ".reg .pred p;\n\t"
            "mbarrier.try_wait.parity.acquire.cta.shared::cta.b64 p, [%1], %2;\n\t"
            "selp.b32 %0, 1, 0, p;\n\t"
            "}"
            : "=r"(done) : "r"(mb), "r"(0u) : "memory");
        if (!done) {
            asm volatile(
                "{\n\t"
                ".reg .pred P1;\n\t"
                "WAIT_LOOP_%=:\n\t"
                "mbarrier.try_wait.parity.acquire.cta.shared::cta.b64 P1, [%0], %1, 0x989680;\n\t"
                "@P1 bra.uni WAIT_DONE_%=;\n\t"
                "bra.uni WAIT_LOOP_%=;\n\t"
                "WAIT_DONE_%=:\n\t"
                "}"
                :: "r"(mb), "r"(0u) : "memory");
        }
    }

    // SMEM path: 8 features, conflict-free LDS.128.
    #pragma unroll
    for (int j = 0; j < K_BULK; ++j) {
        const float4 w = ((const float4*)sW[j])[tid];
        const float  v = sVal[K_LDG + j];
        a.x = fmaf(w.x, v, a.x);
        a.y = fmaf(w.y, v, a.y);
        a.z = fmaf(w.z, v, a.z);
        a.w = fmaf(w.w, v, a.w);
    }

    // Streaming store: written once, never re-read.
    __stcs(out4 + (size_t)r * D4 + c, a);
}

extern "C" void kernel_launch(void* const* d_in, const int* in_sizes, int n_in,
                              void* d_out, int out_size)
{
    // metadata order:
    //   0: feature_indices_0  int32  [4096, 32]
    //   1: feature_values_0   f32    [4096, 32]
    //   2: feature_indices_1  int32  [4096, 32]
    //   3: feature_values_1   f32    [4096, 32]
    //   4: merged_weight      f32    [45056, 1032]
    //   5: bias               f32    [1032]
    const int*    idx0 = (const int*)   d_in[0];
    const float*  val0 = (const float*) d_in[1];
    const int*    idx1 = (const int*)   d_in[2];
    const float*  val1 = (const float*) d_in[3];
    const float4* W4   = (const float4*)d_in[4];
    const float4* b4   = (const float4*)d_in[5];

    float4* out = (float4*)d_out;   // [8192, 1032] : out0 then out1

    dim3 grid(2 * BATCH, NCHUNK);
    ft_hybrid_kernel<<<grid, THREADS>>>(idx0, val0, idx1, val1, W4, b4, out);
}

// round 9
// speedup vs baseline: 1.1389x; 1.1389x over previous
#include <cuda_runtime.h>

#define NUM_OUTPUTS 1032
#define D4 258              // 1032 floats = 258 float4 per weight row
#define CHUNK 86            // float4 per column chunk (3 chunks: 86*3 = 258)
#define NCHUNK 3
#define MAX_ACTIVE 32
#define BATCH 4096
#define THREADS 96          // 3 warps; lanes 0..85 active
#define MINBLOCKS 12        // relax ptxas reg cap: 65536/(96*12) = 56 regs

__global__ __launch_bounds__(THREADS, MINBLOCKS)
void ft_dual_kernel(const int*    __restrict__ idx0,
                    const float*  __restrict__ val0,
                    const int*    __restrict__ idx1,
                    const float*  __restrict__ val1,
                    const float4* __restrict__ W4,
                    const float4* __restrict__ bias4,
                    float4*       __restrict__ out4)
{
    const int row   = blockIdx.x;          // 0..4095 : handles BOTH feature sets
    const int chunk = blockIdx.y;          // 0..2    : slow dim -> L2 phases
    const int tid   = threadIdx.x;

    __shared__ int   sOffA[MAX_ACTIVE], sOffB[MAX_ACTIVE];   // float4-unit offsets
    __shared__ float sValA[MAX_ACTIVE], sValB[MAX_ACTIVE];

    if (tid < MAX_ACTIVE) {
        sOffA[tid] = idx0[row * MAX_ACTIVE + tid] * D4;
        sValA[tid] = val0[row * MAX_ACTIVE + tid];
    } else if (tid < 2 * MAX_ACTIVE) {
        const int t = tid - MAX_ACTIVE;
        sOffB[t] = idx1[row * MAX_ACTIVE + t] * D4;
        sValB[t] = val1[row * MAX_ACTIVE + t];
    }
    __syncthreads();

    if (tid >= CHUNK) return;              // no barriers below

    const int c = chunk * CHUNK + tid;     // float4 column index, 0..257
    const float4* __restrict__ Wc = W4 + c;

    const float4 b = bias4[c];
    float4 a0 = b;                          // accumulator, feature set 0
    float4 a1 = b;                          // accumulator, feature set 1

    #pragma unroll 4
    for (int k = 0; k < MAX_ACTIVE; ++k) {
        // Two independent gather streams -> 2 in-flight LDG.128 per iter,
        // x4 unroll = 8 independent loads per group (regs now available).
        const float4 w0 = __ldg(Wc + sOffA[k]);
        const float4 w1 = __ldg(Wc + sOffB[k]);
        const float  v0 = sValA[k];
        const float  v1 = sValB[k];
        a0.x = fmaf(w0.x, v0, a0.x);
        a0.y = fmaf(w0.y, v0, a0.y);
        a0.z = fmaf(w0.z, v0, a0.z);
        a0.w = fmaf(w0.w, v0, a0.w);
        a1.x = fmaf(w1.x, v1, a1.x);
        a1.y = fmaf(w1.y, v1, a1.y);
        a1.z = fmaf(w1.z, v1, a1.z);
        a1.w = fmaf(w1.w, v1, a1.w);
    }

    // Streaming stores: written once, never re-read.
    __stcs(out4 + (size_t)row * D4 + c, a0);                       // out0
    __stcs(out4 + (size_t)(row + BATCH) * D4 + c, a1);             // out1

}

extern "C" void kernel_launch(void* const* d_in, const int* in_sizes, int n_in,
                              void* d_out, int out_size)
{
    // metadata order:
    //   0: feature_indices_0  int32  [4096, 32]
    //   1: feature_values_0   f32    [4096, 32]
    //   2: feature_indices_1  int32  [4096, 32]
    //   3: feature_values_1   f32    [4096, 32]
    //   4: merged_weight      f32    [45056, 1032]
    //   5: bias               f32    [1032]
    const int*    idx0 = (const int*)   d_in[0];
    const float*  val0 = (const float*) d_in[1];
    const int*    idx1 = (const int*)   d_in[2];
    const float*  val1 = (const float*) d_in[3];
    const float4* W4   = (const float4*)d_in[4];
    const float4* b4   = (const float4*)d_in[5];

    float4* out = (float4*)d_out;   // [8192, 1032] : out0 then out1

    dim3 grid(BATCH, NCHUNK);
    ft_dual_kernel<<<grid, THREADS>>>(idx0, val0, idx1, val1, W4, b4, out);
}